// round 10
// baseline (speedup 1.0000x reference)
#include <cuda_runtime.h>
#include <cuda_fp16.h>
#include <cuda_bf16.h>

// GCN: 2-layer graph conv, N=100000, E=1.6M, 128 -> 32 -> 32.
// Round 10: quad-shuffle gathers — each 4-lane quad loads csr/norm ONCE per edge
// and broadcasts via __shfl_sync(width=4); lanes load only their own h column.
// Gather LDG count drops 45%.
//   side stream : gemm1 (feat @ W1 -> g_hh fp16, UNSCALED)
//   main stream : zero -> degrees -> scanA(+norms) -> scanB -> scatter
//   join
//   gather0     : g_t = relu((sum g_hh[s]*norm_out[s]) * ni + b1)   [fp32]
//   mid         : g_hh2 = (g_t @ W2) * norm_out                     [fp16]
//   gather_out  : d_out = (sum g_hh2[s]) * ni + b2                  [fp32]

#define MAXN 100000
#define MAXE 1600000
#define SCAN_B 512

__device__ int    g_deg_out[MAXN];
__device__ int    g_deg_in[MAXN];
__device__ float  g_norm_out[MAXN];
__device__ float  g_norm_in[MAXN];
__device__ int    g_offset[MAXN];
__device__ int    g_cursor[MAXN];
__device__ int    g_csr[MAXE];
__device__ int    g_blocksums[(MAXN + SCAN_B - 1) / SCAN_B];
__device__ uint4  g_hh [MAXN * 4];     // fp16 h rows: 64B = 4 uint4
__device__ uint4  g_hh2[MAXN * 4];     // fp16 h2 rows
__device__ float4 g_t[MAXN * 8];       // layer-1 activations (fp32)

// ---- helpers ----
__device__ __forceinline__ uint2 pack_h4(float4 a) {
    __half2 lo = __floats2half2_rn(a.x, a.y);
    __half2 hi = __floats2half2_rn(a.z, a.w);
    uint2 u;
    u.x = *(const unsigned int*)&lo;
    u.y = *(const unsigned int*)&hi;
    return u;
}
// acc[0..7] += unpack8(u) * s
__device__ __forceinline__ void acc_h8(float* acc, uint4 u, float s) {
    float2 f0 = __half22float2(*(const __half2*)&u.x);
    float2 f1 = __half22float2(*(const __half2*)&u.y);
    float2 f2 = __half22float2(*(const __half2*)&u.z);
    float2 f3 = __half22float2(*(const __half2*)&u.w);
    acc[0] += f0.x * s; acc[1] += f0.y * s;
    acc[2] += f1.x * s; acc[3] += f1.y * s;
    acc[4] += f2.x * s; acc[5] += f2.y * s;
    acc[6] += f3.x * s; acc[7] += f3.y * s;
}

// ---------------------------------------------------------------- zero
__global__ void zero_kernel(int n) {
    int i = blockIdx.x * blockDim.x + threadIdx.x;
    if (i < n) { g_deg_out[i] = 0; g_deg_in[i] = 0; g_cursor[i] = 0; }
}

// ---------------------------------------------------------------- degrees
__global__ void degree_kernel(const int* __restrict__ src,
                              const int* __restrict__ dst, int E) {
    int e = blockIdx.x * blockDim.x + threadIdx.x;
    if (e < E) {
        atomicAdd(&g_deg_out[src[e]], 1);
        atomicAdd(&g_deg_in[dst[e]], 1);
    }
}

// ---------------------------------------------------------------- scanA + norms
__global__ __launch_bounds__(SCAN_B) void scanA_norm_kernel(int n) {
    __shared__ int swarp[16];
    int t = threadIdx.x;
    int i = blockIdx.x * SCAN_B + t;
    int v = 0;
    if (i < n) {
        int din = g_deg_in[i];
        v = din;
        g_norm_in[i]  = rsqrtf(fmaxf((float)din, 1.f));
        g_norm_out[i] = rsqrtf(fmaxf((float)g_deg_out[i], 1.f));
    }
    int lane = t & 31, w = t >> 5;
    int x = v;
    #pragma unroll
    for (int d = 1; d < 32; d <<= 1) {
        int y = __shfl_up_sync(0xffffffffu, x, d);
        if (lane >= d) x += y;
    }
    if (lane == 31) swarp[w] = x;
    __syncthreads();
    if (w == 0 && t < 16) {
        int y = swarp[t];
        #pragma unroll
        for (int d = 1; d < 16; d <<= 1) {
            int z = __shfl_up_sync(0xffffu, y, d);
            if (t >= d) y += z;
        }
        swarp[t] = y;
    }
    __syncthreads();
    int base = (w > 0) ? swarp[w - 1] : 0;
    int incl = x + base;
    if (i < n) g_offset[i] = incl - v;
    if (t == SCAN_B - 1) g_blocksums[blockIdx.x] = incl;
}

// ---------------------------------------------------------------- scanB
__global__ __launch_bounds__(256) void scanB_kernel(int nb) {
    __shared__ int swarp[8];
    int t = threadIdx.x;
    int v = (t < nb) ? g_blocksums[t] : 0;
    int lane = t & 31, w = t >> 5;
    int x = v;
    #pragma unroll
    for (int d = 1; d < 32; d <<= 1) {
        int y = __shfl_up_sync(0xffffffffu, x, d);
        if (lane >= d) x += y;
    }
    if (lane == 31) swarp[w] = x;
    __syncthreads();
    if (w == 0 && t < 8) {
        int y = swarp[t];
        #pragma unroll
        for (int d = 1; d < 8; d <<= 1) {
            int z = __shfl_up_sync(0xffu, y, d);
            if (t >= d) y += z;
        }
        swarp[t] = y;
    }
    __syncthreads();
    int base = (w > 0) ? swarp[w - 1] : 0;
    if (t < nb) g_blocksums[t] = x + base - v;
}

// ---------------------------------------------------------------- CSR scatter
__global__ void scatter_kernel(const int* __restrict__ src,
                               const int* __restrict__ dst, int E) {
    int e = blockIdx.x * blockDim.x + threadIdx.x;
    if (e < E) {
        int d = dst[e];
        int p = atomicAdd(&g_cursor[d], 1);
        g_csr[g_offset[d] + g_blocksums[d >> 9] + p] = src[e];
    }
}

// ---------------------------------------------------------------- GEMM1 (feat @ W1 -> fp16, UNSCALED)
__global__ __launch_bounds__(256) void gemm1_kernel(const float* __restrict__ feat,
                                                    const float* __restrict__ W1, int n) {
    extern __shared__ float4 dyn[];
    float4* sW = dyn;            // [k=128][cg=8]
    float4* sF = dyn + 1024;     // [row=128][k4=32] swizzled
    int t = threadIdx.x;

    for (int i = t; i < 1024; i += 256) sW[i] = ((const float4*)W1)[i];
    int row0 = blockIdx.x * 128;
    #pragma unroll
    for (int j = 0; j < 16; j++) {
        int i = t + j * 256;
        int r = i >> 5, k4 = i & 31;
        int gr = row0 + r;
        float4 v = make_float4(0.f, 0.f, 0.f, 0.f);
        if (gr < n) v = ((const float4*)feat)[gr * 32 + k4];
        sF[r * 32 + (k4 ^ (r & 7))] = v;
    }
    __syncthreads();

    int rt = t >> 3, cg = t & 7;
    int sw = rt & 7;
    const float4* fp0 = &sF[(rt +  0) * 32];
    const float4* fp1 = &sF[(rt + 32) * 32];
    const float4* fp2 = &sF[(rt + 64) * 32];
    const float4* fp3 = &sF[(rt + 96) * 32];

    float4 a0 = make_float4(0.f,0.f,0.f,0.f), a1 = a0, a2 = a0, a3 = a0;

    #pragma unroll 4
    for (int k4 = 0; k4 < 32; k4++) {
        float4 f0 = fp0[k4 ^ sw];
        float4 f1 = fp1[k4 ^ sw];
        float4 f2 = fp2[k4 ^ sw];
        float4 f3 = fp3[k4 ^ sw];
        #pragma unroll
        for (int i = 0; i < 4; i++) {
            float4 w = sW[(k4 * 4 + i) * 8 + cg];
            float c0 = (i == 0) ? f0.x : (i == 1) ? f0.y : (i == 2) ? f0.z : f0.w;
            float c1 = (i == 0) ? f1.x : (i == 1) ? f1.y : (i == 2) ? f1.z : f1.w;
            float c2 = (i == 0) ? f2.x : (i == 1) ? f2.y : (i == 2) ? f2.z : f2.w;
            float c3 = (i == 0) ? f3.x : (i == 1) ? f3.y : (i == 2) ? f3.z : f3.w;
            a0.x += c0*w.x; a0.y += c0*w.y; a0.z += c0*w.z; a0.w += c0*w.w;
            a1.x += c1*w.x; a1.y += c1*w.y; a1.z += c1*w.z; a1.w += c1*w.w;
            a2.x += c2*w.x; a2.y += c2*w.y; a2.z += c2*w.z; a2.w += c2*w.w;
            a3.x += c3*w.x; a3.y += c3*w.y; a3.z += c3*w.z; a3.w += c3*w.w;
        }
    }

    uint2* hh = (uint2*)g_hh;
    int gr;
    gr = row0 + rt;      if (gr < n) hh[gr * 8 + cg] = pack_h4(a0);
    gr = row0 + rt + 32; if (gr < n) hh[gr * 8 + cg] = pack_h4(a1);
    gr = row0 + rt + 64; if (gr < n) hh[gr * 8 + cg] = pack_h4(a2);
    gr = row0 + rt + 96; if (gr < n) hh[gr * 8 + cg] = pack_h4(a3);
}

// ---------------------------------------------------------------- gather0 (quad-shuffle)
// 4 threads/dst. Lane c loads csr[j+c] + norm once; shfl(width=4) broadcasts.
// All 4 lanes of a quad share d, so they exit together -> quad shfl mask safe.
__global__ __launch_bounds__(256) void gather0_kernel(const float* __restrict__ b1, int n) {
    int tid = blockIdx.x * blockDim.x + threadIdx.x;
    int d = tid >> 2;
    if (d >= n) return;
    int c = tid & 3;
    unsigned qmask = 0xFu << (threadIdx.x & 28);
    int j = g_offset[d] + g_blocksums[d >> 9];
    int e = j + g_deg_in[d];

    float acc[8] = {0.f, 0.f, 0.f, 0.f, 0.f, 0.f, 0.f, 0.f};
    for (; j + 3 < e; j += 4) {
        int   myS = __ldg(&g_csr[j + c]);
        float myN = __ldg(&g_norm_out[myS]);
        #pragma unroll
        for (int k = 0; k < 4; k++) {
            int   s  = __shfl_sync(qmask, myS, k, 4);
            float ns = __shfl_sync(qmask, myN, k, 4);
            uint4 u = g_hh[s * 4 + c];
            acc_h8(acc, u, ns);
        }
    }
    int rem = e - j;
    if (rem > 0) {
        int   myS = 0;
        float myN = 0.f;
        if (c < rem) {
            myS = __ldg(&g_csr[j + c]);
            myN = __ldg(&g_norm_out[myS]);
        }
        for (int k = 0; k < rem; k++) {
            int   s  = __shfl_sync(qmask, myS, k, 4);
            float ns = __shfl_sync(qmask, myN, k, 4);
            uint4 u = g_hh[s * 4 + c];
            acc_h8(acc, u, ns);
        }
    }

    float ni = g_norm_in[d];
    float4 bA = ((const float4*)b1)[c * 2];
    float4 bB = ((const float4*)b1)[c * 2 + 1];
    float4 tA, tB;
    tA.x = fmaxf(acc[0] * ni + bA.x, 0.f);
    tA.y = fmaxf(acc[1] * ni + bA.y, 0.f);
    tA.z = fmaxf(acc[2] * ni + bA.z, 0.f);
    tA.w = fmaxf(acc[3] * ni + bA.w, 0.f);
    tB.x = fmaxf(acc[4] * ni + bB.x, 0.f);
    tB.y = fmaxf(acc[5] * ni + bB.y, 0.f);
    tB.z = fmaxf(acc[6] * ni + bB.z, 0.f);
    tB.w = fmaxf(acc[7] * ni + bB.w, 0.f);
    g_t[d * 8 + c * 2]     = tA;
    g_t[d * 8 + c * 2 + 1] = tB;
}

// ---------------------------------------------------------------- mid GEMM (g_t @ W2 -> fp16, * norm_out)
__global__ __launch_bounds__(256) void mid_kernel(const float* __restrict__ W2, int n) {
    __shared__ float4 sW2[32 * 8];
    __shared__ float4 sT[128 * 8];
    int t = threadIdx.x;
    sW2[t] = ((const float4*)W2)[t];
    int row0 = blockIdx.x * 128;
    #pragma unroll
    for (int j = 0; j < 4; j++) {
        int i = t + j * 256;
        int r = i >> 3, k4 = i & 7;
        int gr = row0 + r;
        float4 v = make_float4(0.f, 0.f, 0.f, 0.f);
        if (gr < n) v = g_t[gr * 8 + k4];
        sT[r * 8 + (k4 ^ (r & 7))] = v;
    }
    __syncthreads();

    int rt = t >> 3, cg = t & 7;
    int sw = rt & 7;
    const float4* fp0 = &sT[(rt +  0) * 8];
    const float4* fp1 = &sT[(rt + 32) * 8];
    const float4* fp2 = &sT[(rt + 64) * 8];
    const float4* fp3 = &sT[(rt + 96) * 8];

    float4 a0 = make_float4(0.f,0.f,0.f,0.f), a1 = a0, a2 = a0, a3 = a0;

    #pragma unroll
    for (int k4 = 0; k4 < 8; k4++) {
        float4 f0 = fp0[k4 ^ sw];
        float4 f1 = fp1[k4 ^ sw];
        float4 f2 = fp2[k4 ^ sw];
        float4 f3 = fp3[k4 ^ sw];
        #pragma unroll
        for (int i = 0; i < 4; i++) {
            float4 w = sW2[(k4 * 4 + i) * 8 + cg];
            float c0 = (i == 0) ? f0.x : (i == 1) ? f0.y : (i == 2) ? f0.z : f0.w;
            float c1 = (i == 0) ? f1.x : (i == 1) ? f1.y : (i == 2) ? f1.z : f1.w;
            float c2 = (i == 0) ? f2.x : (i == 1) ? f2.y : (i == 2) ? f2.z : f2.w;
            float c3 = (i == 0) ? f3.x : (i == 1) ? f3.y : (i == 2) ? f3.z : f3.w;
            a0.x += c0*w.x; a0.y += c0*w.y; a0.z += c0*w.z; a0.w += c0*w.w;
            a1.x += c1*w.x; a1.y += c1*w.y; a1.z += c1*w.z; a1.w += c1*w.w;
            a2.x += c2*w.x; a2.y += c2*w.y; a2.z += c2*w.z; a2.w += c2*w.w;
            a3.x += c3*w.x; a3.y += c3*w.y; a3.z += c3*w.z; a3.w += c3*w.w;
        }
    }

    uint2* hh2 = (uint2*)g_hh2;
    #pragma unroll
    for (int j = 0; j < 4; j++) {
        int gr = row0 + rt + 32 * j;
        if (gr < n) {
            float ns = g_norm_out[gr];
            float4 a = (j == 0) ? a0 : (j == 1) ? a1 : (j == 2) ? a2 : a3;
            a.x *= ns; a.y *= ns; a.z *= ns; a.w *= ns;
            hh2[gr * 8 + cg] = pack_h4(a);
        }
    }
}

// ---------------------------------------------------------------- gather -> output (quad-shuffle)
__global__ __launch_bounds__(256) void gather_out_kernel(const float* __restrict__ b2,
                                                         float4* __restrict__ outp, int n) {
    int tid = blockIdx.x * blockDim.x + threadIdx.x;
    int d = tid >> 2;
    if (d >= n) return;
    int c = tid & 3;
    unsigned qmask = 0xFu << (threadIdx.x & 28);
    int j = g_offset[d] + g_blocksums[d >> 9];
    int e = j + g_deg_in[d];

    float acc[8] = {0.f, 0.f, 0.f, 0.f, 0.f, 0.f, 0.f, 0.f};
    for (; j + 3 < e; j += 4) {
        int myS = __ldg(&g_csr[j + c]);
        #pragma unroll
        for (int k = 0; k < 4; k++) {
            int s = __shfl_sync(qmask, myS, k, 4);
            uint4 u = g_hh2[s * 4 + c];
            acc_h8(acc, u, 1.f);
        }
    }
    int rem = e - j;
    if (rem > 0) {
        int myS = 0;
        if (c < rem) myS = __ldg(&g_csr[j + c]);
        for (int k = 0; k < rem; k++) {
            int s = __shfl_sync(qmask, myS, k, 4);
            uint4 u = g_hh2[s * 4 + c];
            acc_h8(acc, u, 1.f);
        }
    }

    float ni = g_norm_in[d];
    float4 bA = ((const float4*)b2)[c * 2];
    float4 bB = ((const float4*)b2)[c * 2 + 1];
    float4 oA, oB;
    oA.x = acc[0] * ni + bA.x;
    oA.y = acc[1] * ni + bA.y;
    oA.z = acc[2] * ni + bA.z;
    oA.w = acc[3] * ni + bA.w;
    oB.x = acc[4] * ni + bB.x;
    oB.y = acc[5] * ni + bB.y;
    oB.z = acc[6] * ni + bB.z;
    oB.w = acc[7] * ni + bB.w;
    outp[d * 8 + c * 2]     = oA;
    outp[d * 8 + c * 2 + 1] = oB;
}

// ---------------------------------------------------------------- launch
namespace {
struct Ctx {
    cudaStream_t side;
    cudaEvent_t eFork, eJoin;
    Ctx() {
        cudaStreamCreateWithFlags(&side, cudaStreamNonBlocking);
        cudaEventCreateWithFlags(&eFork, cudaEventDisableTiming);
        cudaEventCreateWithFlags(&eJoin, cudaEventDisableTiming);
        cudaFuncSetAttribute(gemm1_kernel,
                             cudaFuncAttributeMaxDynamicSharedMemorySize, 81920);
    }
};
}

extern "C" void kernel_launch(void* const* d_in, const int* in_sizes, int n_in,
                              void* d_out, int out_size) {
    static Ctx ctx;   // resource init only (streams/events/attr), no cached work

    const float* feat = (const float*)d_in[0];
    const float* W1   = (const float*)d_in[1];
    const float* b1   = (const float*)d_in[2];
    const float* W2   = (const float*)d_in[3];
    const float* b2   = (const float*)d_in[4];
    const int*   src  = (const int*)d_in[5];
    const int*   dst  = (const int*)d_in[6];
    float4* out = (float4*)d_out;

    int n = in_sizes[0] / 128;
    int E = in_sizes[5];

    const int B = 256;
    int gblocks = (n + 127) / 128;
    int nb = (n + SCAN_B - 1) / SCAN_B;

    // Fork: gemm1 (independent of graph structure) on side stream.
    cudaEventRecord(ctx.eFork, 0);
    cudaStreamWaitEvent(ctx.side, ctx.eFork, 0);
    gemm1_kernel<<<gblocks, 256, 81920, ctx.side>>>(feat, W1, n);
    cudaEventRecord(ctx.eJoin, ctx.side);

    // Main stream: degrees -> scan(+norms) -> CSR (hidden under gemm1).
    zero_kernel      <<<(n + B - 1) / B, B>>>(n);
    degree_kernel    <<<(E + B - 1) / B, B>>>(src, dst, E);
    scanA_norm_kernel<<<nb, SCAN_B>>>(n);
    scanB_kernel     <<<1, 256>>>(nb);
    scatter_kernel   <<<(E + B - 1) / B, B>>>(src, dst, E);

    // Join: gather0 needs g_hh (gemm1) + norms/CSR (main chain).
    cudaStreamWaitEvent(0, ctx.eJoin, 0);

    gather0_kernel   <<<(n * 4 + B - 1) / B, B>>>(b1, n);
    mid_kernel       <<<gblocks, 256>>>(W2, n);
    gather_out_kernel<<<(n * 4 + B - 1) / B, B>>>(b2, out, n);
}

// round 11
// speedup vs baseline: 1.0050x; 1.0050x over previous
#include <cuda_runtime.h>
#include <cuda_fp16.h>
#include <cuda_bf16.h>

// GCN: 2-layer graph conv, N=100000, E=1.6M, 128 -> 32 -> 32.
// Round 11: revert quad-shuffle (R10 regression); R9 gathers + software-pipelined
// csr/norm prefetch (breaks csr->h dependency chain); int4-vectorized degree kernel.
//   side stream : gemm1 (feat @ W1 -> g_hh fp16, UNSCALED)
//   main stream : zero -> degrees(int4) -> scanA(+norms) -> scanB -> scatter
//   join
//   gather0     : g_t = relu((sum g_hh[s]*norm_out[s]) * ni + b1)   [fp32]
//   mid         : g_hh2 = (g_t @ W2) * norm_out                     [fp16]
//   gather_out  : d_out = (sum g_hh2[s]) * ni + b2                  [fp32]

#define MAXN 100000
#define MAXE 1600000
#define SCAN_B 512

__device__ int    g_deg_out[MAXN];
__device__ int    g_deg_in[MAXN];
__device__ float  g_norm_out[MAXN];
__device__ float  g_norm_in[MAXN];
__device__ int    g_offset[MAXN];
__device__ int    g_cursor[MAXN];
__device__ int    g_csr[MAXE];
__device__ int    g_blocksums[(MAXN + SCAN_B - 1) / SCAN_B];
__device__ uint4  g_hh [MAXN * 4];     // fp16 h rows: 64B = 4 uint4
__device__ uint4  g_hh2[MAXN * 4];     // fp16 h2 rows
__device__ float4 g_t[MAXN * 8];       // layer-1 activations (fp32)

// ---- helpers ----
__device__ __forceinline__ uint2 pack_h4(float4 a) {
    __half2 lo = __floats2half2_rn(a.x, a.y);
    __half2 hi = __floats2half2_rn(a.z, a.w);
    uint2 u;
    u.x = *(const unsigned int*)&lo;
    u.y = *(const unsigned int*)&hi;
    return u;
}
// acc[0..7] += unpack8(u) * s
__device__ __forceinline__ void acc_h8(float* acc, uint4 u, float s) {
    float2 f0 = __half22float2(*(const __half2*)&u.x);
    float2 f1 = __half22float2(*(const __half2*)&u.y);
    float2 f2 = __half22float2(*(const __half2*)&u.z);
    float2 f3 = __half22float2(*(const __half2*)&u.w);
    acc[0] += f0.x * s; acc[1] += f0.y * s;
    acc[2] += f1.x * s; acc[3] += f1.y * s;
    acc[4] += f2.x * s; acc[5] += f2.y * s;
    acc[6] += f3.x * s; acc[7] += f3.y * s;
}

// ---------------------------------------------------------------- zero
__global__ void zero_kernel(int n) {
    int i = blockIdx.x * blockDim.x + threadIdx.x;
    if (i < n) { g_deg_out[i] = 0; g_deg_in[i] = 0; g_cursor[i] = 0; }
}

// ---------------------------------------------------------------- degrees (int4, 4 edges/thread)
__global__ void degree_kernel(const int* __restrict__ src,
                              const int* __restrict__ dst, int E) {
    int i = blockIdx.x * blockDim.x + threadIdx.x;
    int base = i * 4;
    if (base + 3 < E) {
        int4 s = *(const int4*)&src[base];
        int4 d = *(const int4*)&dst[base];
        atomicAdd(&g_deg_out[s.x], 1);
        atomicAdd(&g_deg_out[s.y], 1);
        atomicAdd(&g_deg_out[s.z], 1);
        atomicAdd(&g_deg_out[s.w], 1);
        atomicAdd(&g_deg_in[d.x], 1);
        atomicAdd(&g_deg_in[d.y], 1);
        atomicAdd(&g_deg_in[d.z], 1);
        atomicAdd(&g_deg_in[d.w], 1);
    } else {
        for (int e = base; e < E; e++) {
            atomicAdd(&g_deg_out[src[e]], 1);
            atomicAdd(&g_deg_in[dst[e]], 1);
        }
    }
}

// ---------------------------------------------------------------- scanA + norms
__global__ __launch_bounds__(SCAN_B) void scanA_norm_kernel(int n) {
    __shared__ int swarp[16];
    int t = threadIdx.x;
    int i = blockIdx.x * SCAN_B + t;
    int v = 0;
    if (i < n) {
        int din = g_deg_in[i];
        v = din;
        g_norm_in[i]  = rsqrtf(fmaxf((float)din, 1.f));
        g_norm_out[i] = rsqrtf(fmaxf((float)g_deg_out[i], 1.f));
    }
    int lane = t & 31, w = t >> 5;
    int x = v;
    #pragma unroll
    for (int d = 1; d < 32; d <<= 1) {
        int y = __shfl_up_sync(0xffffffffu, x, d);
        if (lane >= d) x += y;
    }
    if (lane == 31) swarp[w] = x;
    __syncthreads();
    if (w == 0 && t < 16) {
        int y = swarp[t];
        #pragma unroll
        for (int d = 1; d < 16; d <<= 1) {
            int z = __shfl_up_sync(0xffffu, y, d);
            if (t >= d) y += z;
        }
        swarp[t] = y;
    }
    __syncthreads();
    int base = (w > 0) ? swarp[w - 1] : 0;
    int incl = x + base;
    if (i < n) g_offset[i] = incl - v;
    if (t == SCAN_B - 1) g_blocksums[blockIdx.x] = incl;
}

// ---------------------------------------------------------------- scanB
__global__ __launch_bounds__(256) void scanB_kernel(int nb) {
    __shared__ int swarp[8];
    int t = threadIdx.x;
    int v = (t < nb) ? g_blocksums[t] : 0;
    int lane = t & 31, w = t >> 5;
    int x = v;
    #pragma unroll
    for (int d = 1; d < 32; d <<= 1) {
        int y = __shfl_up_sync(0xffffffffu, x, d);
        if (lane >= d) x += y;
    }
    if (lane == 31) swarp[w] = x;
    __syncthreads();
    if (w == 0 && t < 8) {
        int y = swarp[t];
        #pragma unroll
        for (int d = 1; d < 8; d <<= 1) {
            int z = __shfl_up_sync(0xffu, y, d);
            if (t >= d) y += z;
        }
        swarp[t] = y;
    }
    __syncthreads();
    int base = (w > 0) ? swarp[w - 1] : 0;
    if (t < nb) g_blocksums[t] = x + base - v;
}

// ---------------------------------------------------------------- CSR scatter
__global__ void scatter_kernel(const int* __restrict__ src,
                               const int* __restrict__ dst, int E) {
    int e = blockIdx.x * blockDim.x + threadIdx.x;
    if (e < E) {
        int d = dst[e];
        int p = atomicAdd(&g_cursor[d], 1);
        g_csr[g_offset[d] + g_blocksums[d >> 9] + p] = src[e];
    }
}

// ---------------------------------------------------------------- GEMM1 (feat @ W1 -> fp16, UNSCALED)
__global__ __launch_bounds__(256) void gemm1_kernel(const float* __restrict__ feat,
                                                    const float* __restrict__ W1, int n) {
    extern __shared__ float4 dyn[];
    float4* sW = dyn;            // [k=128][cg=8]
    float4* sF = dyn + 1024;     // [row=128][k4=32] swizzled
    int t = threadIdx.x;

    for (int i = t; i < 1024; i += 256) sW[i] = ((const float4*)W1)[i];
    int row0 = blockIdx.x * 128;
    #pragma unroll
    for (int j = 0; j < 16; j++) {
        int i = t + j * 256;
        int r = i >> 5, k4 = i & 31;
        int gr = row0 + r;
        float4 v = make_float4(0.f, 0.f, 0.f, 0.f);
        if (gr < n) v = ((const float4*)feat)[gr * 32 + k4];
        sF[r * 32 + (k4 ^ (r & 7))] = v;
    }
    __syncthreads();

    int rt = t >> 3, cg = t & 7;
    int sw = rt & 7;
    const float4* fp0 = &sF[(rt +  0) * 32];
    const float4* fp1 = &sF[(rt + 32) * 32];
    const float4* fp2 = &sF[(rt + 64) * 32];
    const float4* fp3 = &sF[(rt + 96) * 32];

    float4 a0 = make_float4(0.f,0.f,0.f,0.f), a1 = a0, a2 = a0, a3 = a0;

    #pragma unroll 4
    for (int k4 = 0; k4 < 32; k4++) {
        float4 f0 = fp0[k4 ^ sw];
        float4 f1 = fp1[k4 ^ sw];
        float4 f2 = fp2[k4 ^ sw];
        float4 f3 = fp3[k4 ^ sw];
        #pragma unroll
        for (int i = 0; i < 4; i++) {
            float4 w = sW[(k4 * 4 + i) * 8 + cg];
            float c0 = (i == 0) ? f0.x : (i == 1) ? f0.y : (i == 2) ? f0.z : f0.w;
            float c1 = (i == 0) ? f1.x : (i == 1) ? f1.y : (i == 2) ? f1.z : f1.w;
            float c2 = (i == 0) ? f2.x : (i == 1) ? f2.y : (i == 2) ? f2.z : f2.w;
            float c3 = (i == 0) ? f3.x : (i == 1) ? f3.y : (i == 2) ? f3.z : f3.w;
            a0.x += c0*w.x; a0.y += c0*w.y; a0.z += c0*w.z; a0.w += c0*w.w;
            a1.x += c1*w.x; a1.y += c1*w.y; a1.z += c1*w.z; a1.w += c1*w.w;
            a2.x += c2*w.x; a2.y += c2*w.y; a2.z += c2*w.z; a2.w += c2*w.w;
            a3.x += c3*w.x; a3.y += c3*w.y; a3.z += c3*w.z; a3.w += c3*w.w;
        }
    }

    uint2* hh = (uint2*)g_hh;
    int gr;
    gr = row0 + rt;      if (gr < n) hh[gr * 8 + cg] = pack_h4(a0);
    gr = row0 + rt + 32; if (gr < n) hh[gr * 8 + cg] = pack_h4(a1);
    gr = row0 + rt + 64; if (gr < n) hh[gr * 8 + cg] = pack_h4(a2);
    gr = row0 + rt + 96; if (gr < n) hh[gr * 8 + cg] = pack_h4(a3);
}

// ---------------------------------------------------------------- gather0 (pipelined)
// 4 threads/dst, lane c owns one uint4 of the 64B fp16 row. The NEXT group's
// csr+norm loads are issued before the CURRENT group's h loads, so index
// fetch latency overlaps with feature fetch.
__global__ __launch_bounds__(256) void gather0_kernel(const float* __restrict__ b1, int n) {
    int tid = blockIdx.x * blockDim.x + threadIdx.x;
    int d = tid >> 2;
    if (d >= n) return;
    int c = tid & 3;
    int j = g_offset[d] + g_blocksums[d >> 9];
    int e = j + g_deg_in[d];

    float acc[8] = {0.f, 0.f, 0.f, 0.f, 0.f, 0.f, 0.f, 0.f};

    int s0 = 0, s1 = 0, s2 = 0, s3 = 0;
    float n0 = 0.f, n1 = 0.f, n2 = 0.f, n3 = 0.f;
    bool have = (j + 3 < e);
    if (have) {
        s0 = __ldg(&g_csr[j]);
        s1 = __ldg(&g_csr[j + 1]);
        s2 = __ldg(&g_csr[j + 2]);
        s3 = __ldg(&g_csr[j + 3]);
        n0 = __ldg(&g_norm_out[s0]);
        n1 = __ldg(&g_norm_out[s1]);
        n2 = __ldg(&g_norm_out[s2]);
        n3 = __ldg(&g_norm_out[s3]);
    }
    while (have) {
        int   t0 = s0, t1 = s1, t2 = s2, t3 = s3;
        float m0 = n0, m1 = n1, m2 = n2, m3 = n3;
        j += 4;
        have = (j + 3 < e);
        if (have) {                       // prefetch next group FIRST
            s0 = __ldg(&g_csr[j]);
            s1 = __ldg(&g_csr[j + 1]);
            s2 = __ldg(&g_csr[j + 2]);
            s3 = __ldg(&g_csr[j + 3]);
            n0 = __ldg(&g_norm_out[s0]);
            n1 = __ldg(&g_norm_out[s1]);
            n2 = __ldg(&g_norm_out[s2]);
            n3 = __ldg(&g_norm_out[s3]);
        }
        uint4 u0 = g_hh[t0 * 4 + c];
        uint4 u1 = g_hh[t1 * 4 + c];
        uint4 u2 = g_hh[t2 * 4 + c];
        uint4 u3 = g_hh[t3 * 4 + c];
        acc_h8(acc, u0, m0);
        acc_h8(acc, u1, m1);
        acc_h8(acc, u2, m2);
        acc_h8(acc, u3, m3);
    }
    for (; j < e; j++) {                  // remainder 0..3 edges
        int sx = __ldg(&g_csr[j]);
        float nx = __ldg(&g_norm_out[sx]);
        uint4 ux = g_hh[sx * 4 + c];
        acc_h8(acc, ux, nx);
    }

    float ni = g_norm_in[d];
    float4 bA = ((const float4*)b1)[c * 2];
    float4 bB = ((const float4*)b1)[c * 2 + 1];
    float4 tA, tB;
    tA.x = fmaxf(acc[0] * ni + bA.x, 0.f);
    tA.y = fmaxf(acc[1] * ni + bA.y, 0.f);
    tA.z = fmaxf(acc[2] * ni + bA.z, 0.f);
    tA.w = fmaxf(acc[3] * ni + bA.w, 0.f);
    tB.x = fmaxf(acc[4] * ni + bB.x, 0.f);
    tB.y = fmaxf(acc[5] * ni + bB.y, 0.f);
    tB.z = fmaxf(acc[6] * ni + bB.z, 0.f);
    tB.w = fmaxf(acc[7] * ni + bB.w, 0.f);
    g_t[d * 8 + c * 2]     = tA;
    g_t[d * 8 + c * 2 + 1] = tB;
}

// ---------------------------------------------------------------- mid GEMM (g_t @ W2 -> fp16, * norm_out)
__global__ __launch_bounds__(256) void mid_kernel(const float* __restrict__ W2, int n) {
    __shared__ float4 sW2[32 * 8];
    __shared__ float4 sT[128 * 8];
    int t = threadIdx.x;
    sW2[t] = ((const float4*)W2)[t];
    int row0 = blockIdx.x * 128;
    #pragma unroll
    for (int j = 0; j < 4; j++) {
        int i = t + j * 256;
        int r = i >> 3, k4 = i & 7;
        int gr = row0 + r;
        float4 v = make_float4(0.f, 0.f, 0.f, 0.f);
        if (gr < n) v = g_t[gr * 8 + k4];
        sT[r * 8 + (k4 ^ (r & 7))] = v;
    }
    __syncthreads();

    int rt = t >> 3, cg = t & 7;
    int sw = rt & 7;
    const float4* fp0 = &sT[(rt +  0) * 8];
    const float4* fp1 = &sT[(rt + 32) * 8];
    const float4* fp2 = &sT[(rt + 64) * 8];
    const float4* fp3 = &sT[(rt + 96) * 8];

    float4 a0 = make_float4(0.f,0.f,0.f,0.f), a1 = a0, a2 = a0, a3 = a0;

    #pragma unroll
    for (int k4 = 0; k4 < 8; k4++) {
        float4 f0 = fp0[k4 ^ sw];
        float4 f1 = fp1[k4 ^ sw];
        float4 f2 = fp2[k4 ^ sw];
        float4 f3 = fp3[k4 ^ sw];
        #pragma unroll
        for (int i = 0; i < 4; i++) {
            float4 w = sW2[(k4 * 4 + i) * 8 + cg];
            float c0 = (i == 0) ? f0.x : (i == 1) ? f0.y : (i == 2) ? f0.z : f0.w;
            float c1 = (i == 0) ? f1.x : (i == 1) ? f1.y : (i == 2) ? f1.z : f1.w;
            float c2 = (i == 0) ? f2.x : (i == 1) ? f2.y : (i == 2) ? f2.z : f2.w;
            float c3 = (i == 0) ? f3.x : (i == 1) ? f3.y : (i == 2) ? f3.z : f3.w;
            a0.x += c0*w.x; a0.y += c0*w.y; a0.z += c0*w.z; a0.w += c0*w.w;
            a1.x += c1*w.x; a1.y += c1*w.y; a1.z += c1*w.z; a1.w += c1*w.w;
            a2.x += c2*w.x; a2.y += c2*w.y; a2.z += c2*w.z; a2.w += c2*w.w;
            a3.x += c3*w.x; a3.y += c3*w.y; a3.z += c3*w.z; a3.w += c3*w.w;
        }
    }

    uint2* hh2 = (uint2*)g_hh2;
    #pragma unroll
    for (int j = 0; j < 4; j++) {
        int gr = row0 + rt + 32 * j;
        if (gr < n) {
            float ns = g_norm_out[gr];
            float4 a = (j == 0) ? a0 : (j == 1) ? a1 : (j == 2) ? a2 : a3;
            a.x *= ns; a.y *= ns; a.z *= ns; a.w *= ns;
            hh2[gr * 8 + cg] = pack_h4(a);
        }
    }
}

// ---------------------------------------------------------------- gather -> output (pipelined)
__global__ __launch_bounds__(256) void gather_out_kernel(const float* __restrict__ b2,
                                                         float4* __restrict__ outp, int n) {
    int tid = blockIdx.x * blockDim.x + threadIdx.x;
    int d = tid >> 2;
    if (d >= n) return;
    int c = tid & 3;
    int j = g_offset[d] + g_blocksums[d >> 9];
    int e = j + g_deg_in[d];

    float acc[8] = {0.f, 0.f, 0.f, 0.f, 0.f, 0.f, 0.f, 0.f};

    int s0 = 0, s1 = 0, s2 = 0, s3 = 0;
    bool have = (j + 3 < e);
    if (have) {
        s0 = __ldg(&g_csr[j]);
        s1 = __ldg(&g_csr[j + 1]);
        s2 = __ldg(&g_csr[j + 2]);
        s3 = __ldg(&g_csr[j + 3]);
    }
    while (have) {
        int t0 = s0, t1 = s1, t2 = s2, t3 = s3;
        j += 4;
        have = (j + 3 < e);
        if (have) {                       // prefetch next group FIRST
            s0 = __ldg(&g_csr[j]);
            s1 = __ldg(&g_csr[j + 1]);
            s2 = __ldg(&g_csr[j + 2]);
            s3 = __ldg(&g_csr[j + 3]);
        }
        uint4 u0 = g_hh2[t0 * 4 + c];
        uint4 u1 = g_hh2[t1 * 4 + c];
        uint4 u2 = g_hh2[t2 * 4 + c];
        uint4 u3 = g_hh2[t3 * 4 + c];
        acc_h8(acc, u0, 1.f);
        acc_h8(acc, u1, 1.f);
        acc_h8(acc, u2, 1.f);
        acc_h8(acc, u3, 1.f);
    }
    for (; j < e; j++) {
        int sx = __ldg(&g_csr[j]);
        uint4 ux = g_hh2[sx * 4 + c];
        acc_h8(acc, ux, 1.f);
    }

    float ni = g_norm_in[d];
    float4 bA = ((const float4*)b2)[c * 2];
    float4 bB = ((const float4*)b2)[c * 2 + 1];
    float4 oA, oB;
    oA.x = acc[0] * ni + bA.x;
    oA.y = acc[1] * ni + bA.y;
    oA.z = acc[2] * ni + bA.z;
    oA.w = acc[3] * ni + bA.w;
    oB.x = acc[4] * ni + bB.x;
    oB.y = acc[5] * ni + bB.y;
    oB.z = acc[6] * ni + bB.z;
    oB.w = acc[7] * ni + bB.w;
    outp[d * 8 + c * 2]     = oA;
    outp[d * 8 + c * 2 + 1] = oB;
}

// ---------------------------------------------------------------- launch
namespace {
struct Ctx {
    cudaStream_t side;
    cudaEvent_t eFork, eJoin;
    Ctx() {
        cudaStreamCreateWithFlags(&side, cudaStreamNonBlocking);
        cudaEventCreateWithFlags(&eFork, cudaEventDisableTiming);
        cudaEventCreateWithFlags(&eJoin, cudaEventDisableTiming);
        cudaFuncSetAttribute(gemm1_kernel,
                             cudaFuncAttributeMaxDynamicSharedMemorySize, 81920);
    }
};
}

extern "C" void kernel_launch(void* const* d_in, const int* in_sizes, int n_in,
                              void* d_out, int out_size) {
    static Ctx ctx;   // resource init only (streams/events/attr), no cached work

    const float* feat = (const float*)d_in[0];
    const float* W1   = (const float*)d_in[1];
    const float* b1   = (const float*)d_in[2];
    const float* W2   = (const float*)d_in[3];
    const float* b2   = (const float*)d_in[4];
    const int*   src  = (const int*)d_in[5];
    const int*   dst  = (const int*)d_in[6];
    float4* out = (float4*)d_out;

    int n = in_sizes[0] / 128;
    int E = in_sizes[5];

    const int B = 256;
    int gblocks = (n + 127) / 128;
    int nb = (n + SCAN_B - 1) / SCAN_B;
    int dthreads = (E + 3) / 4;

    // Fork: gemm1 (independent of graph structure) on side stream.
    cudaEventRecord(ctx.eFork, 0);
    cudaStreamWaitEvent(ctx.side, ctx.eFork, 0);
    gemm1_kernel<<<gblocks, 256, 81920, ctx.side>>>(feat, W1, n);
    cudaEventRecord(ctx.eJoin, ctx.side);

    // Main stream: degrees -> scan(+norms) -> CSR (hidden under gemm1).
    zero_kernel      <<<(n + B - 1) / B, B>>>(n);
    degree_kernel    <<<(dthreads + B - 1) / B, B>>>(src, dst, E);
    scanA_norm_kernel<<<nb, SCAN_B>>>(n);
    scanB_kernel     <<<1, 256>>>(nb);
    scatter_kernel   <<<(E + B - 1) / B, B>>>(src, dst, E);

    // Join: gather0 needs g_hh (gemm1) + norms/CSR (main chain).
    cudaStreamWaitEvent(0, ctx.eJoin, 0);

    gather0_kernel   <<<(n * 4 + B - 1) / B, B>>>(b1, n);
    mid_kernel       <<<gblocks, 256>>>(W2, n);
    gather_out_kernel<<<(n * 4 + B - 1) / B, B>>>(b2, out, n);
}